// round 2
// baseline (speedup 1.0000x reference)
#include <cuda_runtime.h>
#include <cuda_bf16.h>

#define N_NODES_C 500000

// Scratch: per-node edge aggregate, padded to float4 so one vector RED per
// edge suffices (w lane wasted). 8 MB -> stays L2-resident during scatter.
__device__ float4 g_agg[N_NODES_C];
__device__ int g_idx_is64;

// ---------------------------------------------------------------------------
// Zero the aggregation buffer (graph replays must be deterministic).
__global__ void __launch_bounds__(256) zero_kernel(int n) {
    int i = blockIdx.x * blockDim.x + threadIdx.x;
    if (i < n) g_agg[i] = make_float4(0.f, 0.f, 0.f, 0.f);
}

// ---------------------------------------------------------------------------
// Detect whether edge_index is int64 or int32 (JAX may have truncated).
// If the data is really int32, interpreting pairs as int64 yields values
// ~b*2^32 >> N_NODES for random b in [0, 500000); 64 samples make a false
// positive astronomically unlikely. Deterministic: same input -> same flag.
__global__ void detect_kernel(const long long* __restrict__ ei) {
    if (blockIdx.x == 0 && threadIdx.x == 0) {
        int ok64 = 1;
        #pragma unroll 1
        for (int k = 0; k < 64; k++) {
            long long v = ei[k];
            if (v < 0 || v >= 1000000000LL) { ok64 = 0; break; }
        }
        g_idx_is64 = ok64;
    }
}

// ---------------------------------------------------------------------------
// Scatter: one vector RED per edge into g_agg[target].
__global__ void __launch_bounds__(256) scatter_kernel(
    const long long* __restrict__ tgt64,
    const int*       __restrict__ tgt32,
    const float*     __restrict__ ea,
    int n_edges)
{
    const bool is64 = (g_idx_is64 != 0);
    int stride = gridDim.x * blockDim.x;
    for (int e = blockIdx.x * blockDim.x + threadIdx.x; e < n_edges; e += stride) {
        long long t = is64 ? __ldcs(tgt64 + e) : (long long)__ldcs(tgt32 + e);
        const float* ep = ea + 3ll * e;
        float a0 = __ldcs(ep + 0);
        float a1 = __ldcs(ep + 1);
        float a2 = __ldcs(ep + 2);
        float* p = reinterpret_cast<float*>(g_agg + t);
        asm volatile("red.global.add.v4.f32 [%0], {%1, %2, %3, %4};"
                     :: "l"(p), "f"(a0), "f"(a1), "f"(a2), "f"(0.0f)
                     : "memory");
    }
}

// ---------------------------------------------------------------------------
// Fused MLP: x=[v0,v1,a0,a1,a2]; h1=relu(W1 x + b1) consumed on the fly into
// h2 accumulators (no h1 array -> low register pressure). Weights in shared,
// all loads are warp-uniform broadcasts (conflict-free).
__global__ void __launch_bounds__(256) mlp_kernel(
    const float2* __restrict__ vattr,
    const float*  __restrict__ W1, const float* __restrict__ b1,
    const float*  __restrict__ W2, const float* __restrict__ b2,
    const float*  __restrict__ W3, const float* __restrict__ b3,
    float* __restrict__ out, int n_nodes)
{
    __shared__ float sW1[250];
    __shared__ float sb1[50];
    __shared__ float sW2[1000];
    __shared__ float sb2[20];
    __shared__ float sW3[20];
    __shared__ float sb3;

    for (int t = threadIdx.x; t < 250; t += blockDim.x) sW1[t] = W1[t];
    for (int t = threadIdx.x; t < 1000; t += blockDim.x) sW2[t] = W2[t];
    if (threadIdx.x < 50) sb1[threadIdx.x] = b1[threadIdx.x];
    {
        int u = threadIdx.x - 64;
        if (u >= 0 && u < 20) sb2[u] = b2[u];
        int w = threadIdx.x - 96;
        if (w >= 0 && w < 20) sW3[w] = W3[w];
        if (threadIdx.x == 128) sb3 = b3[0];
    }
    __syncthreads();

    int i = blockIdx.x * blockDim.x + threadIdx.x;
    if (i >= n_nodes) return;

    float2 v = __ldg(vattr + i);
    float4 a = g_agg[i];
    float x0 = v.x, x1 = v.y, x2 = a.x, x3 = a.y, x4 = a.z;

    float h2[20];
    #pragma unroll
    for (int m = 0; m < 20; m++) h2[m] = sb2[m];

    #pragma unroll 5
    for (int j = 0; j < 50; j++) {
        const float* w = sW1 + j * 5;
        float s = sb1[j];
        s = fmaf(w[0], x0, s);
        s = fmaf(w[1], x1, s);
        s = fmaf(w[2], x2, s);
        s = fmaf(w[3], x3, s);
        s = fmaf(w[4], x4, s);
        s = fmaxf(s, 0.0f);
        #pragma unroll
        for (int m = 0; m < 20; m++) h2[m] = fmaf(sW2[m * 50 + j], s, h2[m]);
    }

    float o = sb3;
    #pragma unroll
    for (int m = 0; m < 20; m++) o = fmaf(sW3[m], fmaxf(h2[m], 0.0f), o);
    out[i] = o;
}

// ---------------------------------------------------------------------------
extern "C" void kernel_launch(void* const* d_in, const int* in_sizes, int n_in,
                              void* d_out, int out_size) {
    const float*     vattr = (const float*)d_in[0];
    const long long* eidx  = (const long long*)d_in[1];
    const float*     eattr = (const float*)d_in[2];
    const float*     W1    = (const float*)d_in[3];
    const float*     b1    = (const float*)d_in[4];
    const float*     W2    = (const float*)d_in[5];
    const float*     b2    = (const float*)d_in[6];
    const float*     W3    = (const float*)d_in[7];
    const float*     b3    = (const float*)d_in[8];

    int n_nodes = in_sizes[0] / 2;   // vertex_attr: [N, 2]
    int n_edges = in_sizes[2] / 3;   // edge_attr:   [E, 3]

    zero_kernel<<<(n_nodes + 255) / 256, 256>>>(n_nodes);
    detect_kernel<<<1, 32>>>(eidx);

    // Row 1 of edge_index (targets); row 0 never touched (halves index traffic).
    const long long* tgt64 = eidx + n_edges;
    const int*       tgt32 = ((const int*)eidx) + n_edges;

    scatter_kernel<<<2960, 256>>>(tgt64, tgt32, eattr, n_edges);

    mlp_kernel<<<(n_nodes + 255) / 256, 256>>>(
        (const float2*)vattr, W1, b1, W2, b2, W3, b3,
        (float*)d_out, n_nodes);
}

// round 3
// speedup vs baseline: 1.2617x; 1.2617x over previous
#include <cuda_runtime.h>
#include <cuda_bf16.h>

#define N_NODES_C 500000

// Per-node edge aggregate, float4-padded: one red.global.add.v4.f32 per edge.
// 8 MB -> L2-resident during the scatter phase.
__device__ float4 g_agg[N_NODES_C];
__device__ int g_idx_is64;

// ---------------------------------------------------------------------------
__global__ void __launch_bounds__(256) zero_kernel(int n) {
    int i = blockIdx.x * blockDim.x + threadIdx.x;
    if (i < n) g_agg[i] = make_float4(0.f, 0.f, 0.f, 0.f);
}

// ---------------------------------------------------------------------------
// int64 vs int32 index detection (JAX may have emitted either). int32 data
// read as int64 gives values ~b*2^32 >> N_NODES for random b; 64 samples.
__global__ void detect_kernel(const long long* __restrict__ ei) {
    if (blockIdx.x == 0 && threadIdx.x == 0) {
        int ok64 = 1;
        #pragma unroll 1
        for (int k = 0; k < 64; k++) {
            long long v = ei[k];
            if (v < 0 || v >= 1000000000LL) { ok64 = 0; break; }
        }
        g_idx_is64 = ok64;
    }
}

// ---------------------------------------------------------------------------
__device__ __forceinline__ void red_add3(float* p, float a0, float a1, float a2) {
    asm volatile("red.global.add.v4.f32 [%0], {%1, %2, %3, %4};"
                 :: "l"(p), "f"(a0), "f"(a1), "f"(a2), "f"(0.0f)
                 : "memory");
}

// Scatter: 4 edges per thread, all loads vectorized to LDG.128.
__global__ void __launch_bounds__(256) scatter_kernel(
    const longlong2* __restrict__ t64v,
    const int4*      __restrict__ t32v,
    const float4*    __restrict__ ea4,
    const long long* __restrict__ t64s,
    const int*       __restrict__ t32s,
    const float*     __restrict__ eas,
    int n_quads, int n_edges)
{
    const bool is64 = (g_idx_is64 != 0);
    int q = blockIdx.x * blockDim.x + threadIdx.x;
    if (q < n_quads) {
        int i0, i1, i2, i3;
        if (is64) {
            longlong2 a = __ldcs(t64v + 2 * q);
            longlong2 b = __ldcs(t64v + 2 * q + 1);
            i0 = (int)a.x; i1 = (int)a.y; i2 = (int)b.x; i3 = (int)b.y;
        } else {
            int4 a = __ldcs(t32v + q);
            i0 = a.x; i1 = a.y; i2 = a.z; i3 = a.w;
        }
        float4 f0 = __ldcs(ea4 + 3 * q + 0);
        float4 f1 = __ldcs(ea4 + 3 * q + 1);
        float4 f2 = __ldcs(ea4 + 3 * q + 2);
        red_add3((float*)(g_agg + i0), f0.x, f0.y, f0.z);
        red_add3((float*)(g_agg + i1), f0.w, f1.x, f1.y);
        red_add3((float*)(g_agg + i2), f1.z, f1.w, f2.x);
        red_add3((float*)(g_agg + i3), f2.y, f2.z, f2.w);
    }
    // Tail edges (n_edges % 4), handled by the first few threads.
    int rem = n_edges - n_quads * 4;
    int g = blockIdx.x * blockDim.x + threadIdx.x;
    if (g < rem) {
        int e = n_quads * 4 + g;
        long long t = is64 ? t64s[e] : (long long)t32s[e];
        red_add3((float*)(g_agg + t), eas[3 * e], eas[3 * e + 1], eas[3 * e + 2]);
    }
}

// ---------------------------------------------------------------------------
// Fused MLP, LDS-vectorized + packed f32x2 FMAs.
//   W1 in shared as [50][8] (rows padded, 2x LDS.128 per j)
//   W2 in shared TRANSPOSED as [50][20] (5x ld.shared.v2.b64 per j -> ten
//   64-bit weight-pair regs feeding fma.rn.f32x2 directly, no repacking)
//   h2 accumulators: 10x f32x2.
__global__ void __launch_bounds__(256) mlp_kernel(
    const float2* __restrict__ vattr,
    const float*  __restrict__ W1, const float* __restrict__ b1,
    const float*  __restrict__ W2, const float* __restrict__ b2,
    const float*  __restrict__ W3, const float* __restrict__ b3,
    float* __restrict__ out, int n_nodes)
{
    __shared__ __align__(16) float sW1[400];   // [50][8], cols 5..7 = 0
    __shared__ __align__(16) float sW2[1000];  // [50][20] = W2 transposed
    __shared__ float sb1[50];
    __shared__ __align__(16) float sb2[20];
    __shared__ float sW3[20];
    __shared__ float sb3v;

    for (int t = threadIdx.x; t < 400; t += blockDim.x) {
        int j = t >> 3, k = t & 7;
        sW1[t] = (k < 5) ? W1[j * 5 + k] : 0.0f;
    }
    for (int t = threadIdx.x; t < 1000; t += blockDim.x) {
        int j = t / 20, m = t % 20;
        sW2[t] = W2[m * 50 + j];   // transpose: row j holds the 20 m-weights
    }
    if (threadIdx.x < 50) sb1[threadIdx.x] = b1[threadIdx.x];
    {
        int u = threadIdx.x - 64;
        if (u >= 0 && u < 20) sb2[u] = b2[u];
        int w = threadIdx.x - 96;
        if (w >= 0 && w < 20) sW3[w] = W3[w];
        if (threadIdx.x == 128) sb3v = b3[0];
    }
    __syncthreads();

    int i = blockIdx.x * blockDim.x + threadIdx.x;
    if (i >= n_nodes) return;

    float2 v = __ldg(vattr + i);
    float4 a = g_agg[i];
    const float x0 = v.x, x1 = v.y, x2 = a.x, x3 = a.y, x4 = a.z;

    unsigned int w2base = (unsigned int)__cvta_generic_to_shared(sW2);
    unsigned int b2base = (unsigned int)__cvta_generic_to_shared(sb2);
    const float4* sW1v = reinterpret_cast<const float4*>(sW1);

    // h2 accumulators as 10 packed f32x2 (lo = m even, hi = m odd)
    unsigned long long h2p[10];
    #pragma unroll
    for (int p = 0; p < 5; p++) {
        asm("ld.shared.v2.b64 {%0, %1}, [%2];"
            : "=l"(h2p[2 * p]), "=l"(h2p[2 * p + 1])
            : "r"(b2base + p * 16));
    }

    #pragma unroll
    for (int j = 0; j < 50; j++) {
        // ---- layer 1, row j (scalar; 5-dim dot) ----
        float4 wa = sW1v[j * 2];
        float4 wb = sW1v[j * 2 + 1];
        float s = sb1[j];
        s = fmaf(wa.x, x0, s);
        s = fmaf(wa.y, x1, s);
        s = fmaf(wa.z, x2, s);
        s = fmaf(wa.w, x3, s);
        s = fmaf(wb.x, x4, s);
        s = fmaxf(s, 0.0f);

        unsigned long long sd;
        asm("mov.b64 %0, {%1, %1};" : "=l"(sd) : "f"(s));  // (s, s)

        // ---- layer 2, column j: 10 weight pairs via 5x LDS.128 ----
        unsigned int aj = w2base + j * 80;
        unsigned long long w0, w1_, w2_, w3_, w4, w5, w6, w7, w8, w9;
        asm("ld.shared.v2.b64 {%0, %1}, [%2];"    : "=l"(w0), "=l"(w1_) : "r"(aj));
        asm("ld.shared.v2.b64 {%0, %1}, [%2+16];" : "=l"(w2_), "=l"(w3_) : "r"(aj));
        asm("ld.shared.v2.b64 {%0, %1}, [%2+32];" : "=l"(w4), "=l"(w5) : "r"(aj));
        asm("ld.shared.v2.b64 {%0, %1}, [%2+48];" : "=l"(w6), "=l"(w7) : "r"(aj));
        asm("ld.shared.v2.b64 {%0, %1}, [%2+64];" : "=l"(w8), "=l"(w9) : "r"(aj));

        asm("fma.rn.f32x2 %0, %1, %2, %0;" : "+l"(h2p[0]) : "l"(w0),  "l"(sd));
        asm("fma.rn.f32x2 %0, %1, %2, %0;" : "+l"(h2p[1]) : "l"(w1_), "l"(sd));
        asm("fma.rn.f32x2 %0, %1, %2, %0;" : "+l"(h2p[2]) : "l"(w2_), "l"(sd));
        asm("fma.rn.f32x2 %0, %1, %2, %0;" : "+l"(h2p[3]) : "l"(w3_), "l"(sd));
        asm("fma.rn.f32x2 %0, %1, %2, %0;" : "+l"(h2p[4]) : "l"(w4),  "l"(sd));
        asm("fma.rn.f32x2 %0, %1, %2, %0;" : "+l"(h2p[5]) : "l"(w5),  "l"(sd));
        asm("fma.rn.f32x2 %0, %1, %2, %0;" : "+l"(h2p[6]) : "l"(w6),  "l"(sd));
        asm("fma.rn.f32x2 %0, %1, %2, %0;" : "+l"(h2p[7]) : "l"(w7),  "l"(sd));
        asm("fma.rn.f32x2 %0, %1, %2, %0;" : "+l"(h2p[8]) : "l"(w8),  "l"(sd));
        asm("fma.rn.f32x2 %0, %1, %2, %0;" : "+l"(h2p[9]) : "l"(w9),  "l"(sd));
    }

    // ---- layer 3 ----
    float o = sb3v;
    #pragma unroll
    for (int p = 0; p < 10; p++) {
        float lo, hi;
        asm("mov.b64 {%0, %1}, %2;" : "=f"(lo), "=f"(hi) : "l"(h2p[p]));
        o = fmaf(sW3[2 * p],     fmaxf(lo, 0.0f), o);
        o = fmaf(sW3[2 * p + 1], fmaxf(hi, 0.0f), o);
    }
    out[i] = o;
}

// ---------------------------------------------------------------------------
extern "C" void kernel_launch(void* const* d_in, const int* in_sizes, int n_in,
                              void* d_out, int out_size) {
    const float*     vattr = (const float*)d_in[0];
    const long long* eidx  = (const long long*)d_in[1];
    const float*     eattr = (const float*)d_in[2];
    const float*     W1    = (const float*)d_in[3];
    const float*     b1    = (const float*)d_in[4];
    const float*     W2    = (const float*)d_in[5];
    const float*     b2    = (const float*)d_in[6];
    const float*     W3    = (const float*)d_in[7];
    const float*     b3    = (const float*)d_in[8];

    int n_nodes = in_sizes[0] / 2;   // vertex_attr: [N, 2]
    int n_edges = in_sizes[2] / 3;   // edge_attr:   [E, 3]

    zero_kernel<<<(n_nodes + 255) / 256, 256>>>(n_nodes);
    detect_kernel<<<1, 32>>>(eidx);

    // Row 1 of edge_index (targets); row 0 never touched.
    const long long* tgt64 = eidx + n_edges;
    const int*       tgt32 = ((const int*)eidx) + n_edges;

    int n_quads = n_edges / 4;
    int blocks = (n_quads + 255) / 256;
    if (blocks < 1) blocks = 1;
    scatter_kernel<<<blocks, 256>>>(
        (const longlong2*)tgt64, (const int4*)tgt32, (const float4*)eattr,
        tgt64, tgt32, eattr, n_quads, n_edges);

    mlp_kernel<<<(n_nodes + 255) / 256, 256>>>(
        (const float2*)vattr, W1, b1, W2, b2, W3, b3,
        (float*)d_out, n_nodes);
}